// round 1
// baseline (speedup 1.0000x reference)
#include <cuda_runtime.h>
#include <math.h>

#define BB   4
#define TT   2048
#define DD   1024
#define HH   8
#define DHH  64
#define EE   5
#define BT   (BB*TT)     // 8192
#define HD   (HH*DHH)    // 512
#define HE   (HH*EE)     // 40
#define EDH  (EE*DHH)    // 320

// ---------------- scratch (device globals; no allocations allowed) ----------
__device__ float g_q  [BT*HD];
__device__ float g_k  [BT*HD];
__device__ float g_xv [BT*EDH];
__device__ float g_glv[BT*HE];
__device__ float g_glo[BT*HE];
__device__ float g_v  [BT*HD];
__device__ float g_at [BT*HD];
__device__ float g_agg[BT*EDH];

// ---------------- generic fp32 tiled GEMM: C = (accum? C : 0) + A*B ---------
// A: MxK row-major lda, B: KxN row-major ldb, C: MxN row-major ldc.
// 64x64 tile, BK=16, 256 threads, 4x4 per-thread micro-tile.
__global__ __launch_bounds__(256) void sgemm_kernel(
    const float* __restrict__ A, const float* __restrict__ B, float* __restrict__ C,
    int M, int N, int K, int lda, int ldb, int ldc, int accum)
{
    __shared__ float As[16][65];
    __shared__ float Bs[16][65];
    const int bm = blockIdx.y * 64;
    const int bn = blockIdx.x * 64;
    const int tid = threadIdx.x;
    const int tr = tid >> 4;       // 0..15
    const int tc = tid & 15;       // 0..15

    float acc[4][4];
#pragma unroll
    for (int i = 0; i < 4; i++)
#pragma unroll
        for (int j = 0; j < 4; j++) acc[i][j] = 0.f;

    for (int k0 = 0; k0 < K; k0 += 16) {
        // A tile: 64 rows x 16 k  (global reads coalesced along k)
        for (int i = tid; i < 64 * 16; i += 256) {
            int kk = i & 15, m = i >> 4;
            int gm = bm + m, gk = k0 + kk;
            As[kk][m] = (gm < M && gk < K) ? A[(size_t)gm * lda + gk] : 0.f;
        }
        // B tile: 16 k x 64 cols (global reads coalesced along n)
        for (int i = tid; i < 16 * 64; i += 256) {
            int n = i & 63, kk = i >> 6;
            int gk = k0 + kk, gn = bn + n;
            Bs[kk][n] = (gk < K && gn < N) ? B[(size_t)gk * ldb + gn] : 0.f;
        }
        __syncthreads();
#pragma unroll
        for (int kk = 0; kk < 16; kk++) {
            float a[4], b[4];
#pragma unroll
            for (int i = 0; i < 4; i++) a[i] = As[kk][tr * 4 + i];
#pragma unroll
            for (int j = 0; j < 4; j++) b[j] = Bs[kk][tc * 4 + j];
#pragma unroll
            for (int i = 0; i < 4; i++)
#pragma unroll
                for (int j = 0; j < 4; j++) acc[i][j] += a[i] * b[j];
        }
        __syncthreads();
    }

#pragma unroll
    for (int i = 0; i < 4; i++) {
        int gm = bm + tr * 4 + i;
        if (gm >= M) continue;
#pragma unroll
        for (int j = 0; j < 4; j++) {
            int gn = bn + tc * 4 + j;
            if (gn >= N) continue;
            size_t idx = (size_t)gm * ldc + gn;
            C[idx] = accum ? (C[idx] + acc[i][j]) : acc[i][j];
        }
    }
}

// ---------------- top-2 helper ----------------------------------------------
__device__ __forceinline__ void top2_of5(const float g[5], int& i1, int& i2) {
    i1 = 0;
#pragma unroll
    for (int e = 1; e < 5; e++) if (g[e] > g[i1]) i1 = e;
    i2 = (i1 == 0) ? 1 : 0;
#pragma unroll
    for (int e = 0; e < 5; e++) if (e != i1 && g[e] > g[i2]) i2 = e;
}

// ---------------- V combine: v[bt, h*64+d] = sum_topk sigmoid(gl)*xv --------
__global__ void v_combine_kernel(const float* __restrict__ glv,
                                 const float* __restrict__ xv,
                                 float* __restrict__ v)
{
    int idx = blockIdx.x * 256 + threadIdx.x;
    if (idx >= BT * HH * DHH) return;
    int d  = idx & (DHH - 1);
    int h  = (idx >> 6) & (HH - 1);
    int bt = idx >> 9;
    const float* g = glv + (size_t)bt * HE + h * EE;
    float ga[5] = { g[0], g[1], g[2], g[3], g[4] };
    int i1, i2;
    top2_of5(ga, i1, i2);
    float w1 = 1.f / (1.f + __expf(-ga[i1]));
    float w2 = 1.f / (1.f + __expf(-ga[i2]));
    float r = w1 * xv[(size_t)bt * EDH + i1 * DHH + d]
            + w2 * xv[(size_t)bt * EDH + i2 * DHH + d];
    v[(size_t)bt * HD + h * DHH + d] = r;
}

// ---------------- flash attention (fp32, 1 thread = 1 q row) ----------------
// q/k/v/attn all laid out (bt, h*64+d). Non-causal full attention.
__global__ __launch_bounds__(128) void flash_attn_kernel(
    const float* __restrict__ q, const float* __restrict__ k,
    const float* __restrict__ v, float* __restrict__ attn)
{
    const int h = blockIdx.y & (HH - 1);
    const int b = blockIdx.y >> 3;
    const int row = blockIdx.x * 128 + threadIdx.x;   // t index in [0,T)
    __shared__ float Ks[32][64];
    __shared__ float Vs[32][64];

    const size_t btq = (size_t)(b * TT + row);
    float qr[DHH];
#pragma unroll
    for (int d = 0; d < DHH; d++) qr[d] = q[btq * HD + h * DHH + d] * 0.125f;

    float o[DHH];
#pragma unroll
    for (int d = 0; d < DHH; d++) o[d] = 0.f;
    float mrun = -1e30f, lrun = 0.f;

    for (int j0 = 0; j0 < TT; j0 += 32) {
        __syncthreads();
        for (int i = threadIdx.x; i < 32 * 64; i += 128) {
            int jj = i >> 6, d = i & 63;
            size_t btk = (size_t)(b * TT + j0 + jj);
            Ks[jj][d] = k[btk * HD + h * DHH + d];
            Vs[jj][d] = v[btk * HD + h * DHH + d];
        }
        __syncthreads();

        float s[32];
        float mnew = mrun;
#pragma unroll 4
        for (int jj = 0; jj < 32; jj++) {
            const float4* kr = (const float4*)Ks[jj];
            float acc = 0.f;
#pragma unroll
            for (int d4 = 0; d4 < 16; d4++) {
                float4 kk = kr[d4];
                acc += qr[4*d4+0]*kk.x + qr[4*d4+1]*kk.y
                     + qr[4*d4+2]*kk.z + qr[4*d4+3]*kk.w;
            }
            s[jj] = acc;
            mnew = fmaxf(mnew, acc);
        }
        float corr = __expf(mrun - mnew);
        lrun *= corr;
#pragma unroll
        for (int d = 0; d < DHH; d++) o[d] *= corr;
#pragma unroll 2
        for (int jj = 0; jj < 32; jj++) {
            float p = __expf(s[jj] - mnew);
            lrun += p;
            const float4* vr = (const float4*)Vs[jj];
#pragma unroll
            for (int d4 = 0; d4 < 16; d4++) {
                float4 vv = vr[d4];
                o[4*d4+0] += p*vv.x; o[4*d4+1] += p*vv.y;
                o[4*d4+2] += p*vv.z; o[4*d4+3] += p*vv.w;
            }
        }
        mrun = mnew;
    }
    float inv = 1.f / lrun;
#pragma unroll
    for (int d = 0; d < DHH; d++) attn[btq * HD + h * DHH + d] = o[d] * inv;
}

// ---------------- out-gate aggregation: agg[bt,e,d] = sum_h mask*attn -------
__global__ void out_gate_kernel(const float* __restrict__ glo,
                                const float* __restrict__ attn,
                                float* __restrict__ agg)
{
    int idx = blockIdx.x * 256 + threadIdx.x;
    if (idx >= BT * EE * DHH) return;
    int d  = idx % DHH;
    int e  = (idx / DHH) % EE;
    int bt = idx / (EE * DHH);
    float sum = 0.f;
#pragma unroll
    for (int h = 0; h < HH; h++) {
        const float* g = glo + (size_t)bt * HE + h * EE;
        float ga[5] = { g[0], g[1], g[2], g[3], g[4] };
        int i1, i2;
        top2_of5(ga, i1, i2);
        if (e == i1 || e == i2) sum += attn[(size_t)bt * HD + h * DHH + d];
    }
    agg[idx] = sum;
}

// ---------------- launcher ---------------------------------------------------
static inline dim3 gemm_grid(int M, int N) {
    return dim3((unsigned)((N + 63) / 64), (unsigned)((M + 63) / 64));
}

extern "C" void kernel_launch(void* const* d_in, const int* in_sizes, int n_in,
                              void* d_out, int out_size)
{
    const float* x  = (const float*)d_in[0];
    const float* Wq = (const float*)d_in[1];
    const float* Wk = (const float*)d_in[2];
    const float* Ws = (const float*)d_in[3];
    const float* Wd = (const float*)d_in[4];
    const float* Wv = (const float*)d_in[5];
    const float* Wo = (const float*)d_in[6];
    float* out = (float*)d_out;

    float *q, *k, *xv, *glv, *glo, *v, *attn, *agg;
    cudaGetSymbolAddress((void**)&q,    g_q);
    cudaGetSymbolAddress((void**)&k,    g_k);
    cudaGetSymbolAddress((void**)&xv,   g_xv);
    cudaGetSymbolAddress((void**)&glv,  g_glv);
    cudaGetSymbolAddress((void**)&glo,  g_glo);
    cudaGetSymbolAddress((void**)&v,    g_v);
    cudaGetSymbolAddress((void**)&attn, g_at);
    cudaGetSymbolAddress((void**)&agg,  g_agg);

    // Projections
    sgemm_kernel<<<gemm_grid(BT, HD), 256>>>(x, Wq, q,  BT, HD, DD, DD, HD, HD, 0);
    sgemm_kernel<<<gemm_grid(BT, HD), 256>>>(x, Wk, k,  BT, HD, DD, DD, HD, HD, 0);
    sgemm_kernel<<<gemm_grid(BT, HE), 256>>>(x, Ws, glv, BT, HE, DD, DD, HE, HE, 0);
    sgemm_kernel<<<gemm_grid(BT, HE), 256>>>(x, Wd, glo, BT, HE, DD, DD, HE, HE, 0);
    // Expert V projections: xv[bt, e*64+d], one GEMM per expert
    for (int e = 0; e < EE; e++) {
        sgemm_kernel<<<gemm_grid(BT, DHH), 256>>>(
            x, Wv + (size_t)e * DD * DHH, xv + e * DHH,
            BT, DHH, DD, DD, DHH, EDH, 0);
    }
    // V combine (top-2 sigmoid gating)
    {
        int n = BT * HH * DHH;
        v_combine_kernel<<<(n + 255) / 256, 256>>>(glv, xv, v);
    }
    // Flash attention
    flash_attn_kernel<<<dim3(TT / 128, BB * HH), 128>>>(q, k, v, attn);
    // Output gate aggregation over heads
    {
        int n = BT * EE * DHH;
        out_gate_kernel<<<(n + 255) / 256, 256>>>(glo, attn, agg);
    }
    // Output expert GEMMs with accumulation: out = sum_e agg_e @ Wo[e]
    for (int e = 0; e < EE; e++) {
        sgemm_kernel<<<gemm_grid(BT, DD), 256>>>(
            agg + e * DHH, Wo + (size_t)e * DHH * DD, out,
            BT, DD, DHH, EDH, DD, DD, e > 0 ? 1 : 0);
    }
}

// round 3
// speedup vs baseline: 3.3847x; 3.3847x over previous
#include <cuda_runtime.h>
#include <cstdint>

#define BB   4
#define TT   2048
#define DD   1024
#define HH   8
#define DHH  64
#define EE   5
#define BT   (BB*TT)     // 8192
#define HD   (HH*DHH)    // 512
#define NBIG 1536        // padded fused-projection width (1424 real + pad)
// column offsets inside fused projection output
#define C_Q   0
#define C_K   512
#define C_GLV 1024
#define C_GLO 1064
#define C_XV  1104

// ---------------- scratch (device globals; no allocations allowed) ----------
__device__ float g_Bbig[DD*NBIG];      // packed [Wq|Wk|Ws|Wd|Wv|0] fp32
__device__ float g_proj[BT*NBIG];      // fused projection output (fp32)
__device__ float g_v   [BT*HD];
__device__ float g_at  [BT*HD];
__device__ float g_agg [BT*EE*DHH];    // fp32

// ---------------- helpers ----------------------------------------------------
__device__ __forceinline__ uint32_t f2tf32(float x) {
    uint32_t r;
    asm("cvt.rna.tf32.f32 %0, %1;" : "=r"(r) : "f"(x));
    return r;
}
// split fp32 -> (hi, lo) tf32 bit patterns; hi+lo ≈ x to ~21 mantissa bits
__device__ __forceinline__ void tf32_split(float x, uint32_t& hi, uint32_t& lo) {
    hi = f2tf32(x);
    lo = f2tf32(x - __uint_as_float(hi));
}
__device__ __forceinline__ void cp_async16(uint32_t s, const void* g) {
    asm volatile("cp.async.cg.shared.global [%0], [%1], 16;" :: "r"(s), "l"(g));
}
__device__ __forceinline__ void cp_commit() {
    asm volatile("cp.async.commit_group;");
}
__device__ __forceinline__ void cp_wait0() {
    asm volatile("cp.async.wait_group 0;");
}
__device__ __forceinline__ void cp_wait1() {
    asm volatile("cp.async.wait_group 1;");
}
__device__ __forceinline__ void mma_tf32(float* c, const uint32_t* a, const uint32_t* b) {
    asm volatile(
        "mma.sync.aligned.m16n8k8.row.col.f32.tf32.tf32.f32 "
        "{%0,%1,%2,%3}, {%4,%5,%6,%7}, {%8,%9}, {%0,%1,%2,%3};"
        : "+f"(c[0]), "+f"(c[1]), "+f"(c[2]), "+f"(c[3])
        : "r"(a[0]), "r"(a[1]), "r"(a[2]), "r"(a[3]), "r"(b[0]), "r"(b[1]));
}

// ---------------- pack kernel: build fused B matrix (fp32 copy) -------------
__global__ void pack_bbig_kernel(const float* __restrict__ Wq, const float* __restrict__ Wk,
                                 const float* __restrict__ Ws, const float* __restrict__ Wd,
                                 const float* __restrict__ Wv, float* __restrict__ Bb) {
    int idx = blockIdx.x * 256 + threadIdx.x;
    if (idx >= DD * NBIG) return;
    int d = idx / NBIG, c = idx % NBIG;
    float v = 0.f;
    if      (c < 512)  v = Wq[d * 512 + c];
    else if (c < 1024) v = Wk[d * 512 + c - 512];
    else if (c < 1064) v = Ws[d * 40 + c - 1024];
    else if (c < 1104) v = Wd[d * 40 + c - 1064];
    else if (c < 1424) {
        int cc = c - 1104;
        int e = cc >> 6, kk = cc & 63;
        v = Wv[((size_t)e * DD + d) * 64 + kk];
    }
    Bb[idx] = v;
}

// ---------------- 3xTF32 tensor-core GEMM: C = A(MxK)*B(KxN), row-major -----
// BM=128 BN=128 BK=32, 256 threads, warp tile 64x32, cp.async double buffer.
// fp32 inputs, in-register hi/lo tf32 split, 3 MMAs per tile pair -> ~fp32 acc.
#define SA_STRIDE 36
#define SB_STRIDE 136
#define SA_FLOATS (128*SA_STRIDE)   // 4608
#define SB_FLOATS (32*SB_STRIDE)    // 4352
#define GEMM_SMEM_BYTES ((2*SA_FLOATS + 2*SB_FLOATS)*4)  // 71680

__global__ __launch_bounds__(256) void tf32_gemm_kernel(
    const float* __restrict__ A, const float* __restrict__ B, float* __restrict__ C,
    int M, int N, int K, int lda, int ldb, int ldc)
{
    extern __shared__ float smem[];
    float* sA = smem;                       // [2][SA_FLOATS]
    float* sB = smem + 2 * SA_FLOATS;       // [2][SB_FLOATS]

    const int tid  = threadIdx.x;
    const int warp = tid >> 5, lane = tid & 31;
    const int lq = lane >> 2, lr = lane & 3;
    const int wm = (warp & 1) * 64;
    const int wn = (warp >> 1) * 32;
    const int bm = blockIdx.y * 128;
    const int bn = blockIdx.x * 128;

    float acc[4][4][4];
#pragma unroll
    for (int i = 0; i < 4; i++)
#pragma unroll
        for (int j = 0; j < 4; j++)
#pragma unroll
            for (int v = 0; v < 4; v++) acc[i][j][v] = 0.f;

    const uint32_t sA_base = (uint32_t)__cvta_generic_to_shared(sA);
    const uint32_t sB_base = (uint32_t)__cvta_generic_to_shared(sB);

#define COPY_STAGE(buf, k0)                                                     \
    {                                                                           \
        _Pragma("unroll")                                                       \
        for (int it = 0; it < 4; it++) {                                        \
            int f = tid + it * 256;                                             \
            int ar = f >> 3, ac4 = f & 7;                                       \
            cp_async16(sA_base + ((buf) * SA_FLOATS + ar * SA_STRIDE + ac4 * 4) * 4, \
                       A + (size_t)(bm + ar) * lda + (k0) + ac4 * 4);           \
            int br = f >> 5, bc4 = f & 31;                                      \
            cp_async16(sB_base + ((buf) * SB_FLOATS + br * SB_STRIDE + bc4 * 4) * 4, \
                       B + (size_t)((k0) + br) * ldb + bn + bc4 * 4);           \
        }                                                                       \
    }

    const int nk = K >> 5;
    COPY_STAGE(0, 0);
    cp_commit();

    for (int kt = 0; kt < nk; kt++) {
        if (kt + 1 < nk) {
            COPY_STAGE((kt + 1) & 1, (kt + 1) << 5);
            cp_commit();
            cp_wait1();
        } else {
            cp_wait0();
        }
        __syncthreads();

        const float* cA = sA + (kt & 1) * SA_FLOATS;
        const float* cB = sB + (kt & 1) * SB_FLOATS;
#pragma unroll
        for (int s = 0; s < 4; s++) {
            uint32_t ah[4][4], al[4][4], bh[4][2], bl[4][2];
#pragma unroll
            for (int i = 0; i < 4; i++) {
                int base = (wm + i * 16 + lq) * SA_STRIDE + s * 8 + lr;
                tf32_split(cA[base],                  ah[i][0], al[i][0]);
                tf32_split(cA[base + 8 * SA_STRIDE],  ah[i][1], al[i][1]);
                tf32_split(cA[base + 4],              ah[i][2], al[i][2]);
                tf32_split(cA[base + 8*SA_STRIDE+4],  ah[i][3], al[i][3]);
            }
#pragma unroll
            for (int j = 0; j < 4; j++) {
                int base = (s * 8 + lr) * SB_STRIDE + wn + j * 8 + lq;
                tf32_split(cB[base],                  bh[j][0], bl[j][0]);
                tf32_split(cB[base + 4 * SB_STRIDE],  bh[j][1], bl[j][1]);
            }
#pragma unroll
            for (int i = 0; i < 4; i++)
#pragma unroll
                for (int j = 0; j < 4; j++) {
                    mma_tf32(acc[i][j], ah[i], bl[j]);   // hi*lo
                    mma_tf32(acc[i][j], al[i], bh[j]);   // lo*hi
                    mma_tf32(acc[i][j], ah[i], bh[j]);   // hi*hi (last: largest term)
                }
        }
        __syncthreads();
    }
#undef COPY_STAGE

#pragma unroll
    for (int i = 0; i < 4; i++) {
        int r0 = bm + wm + i * 16 + lq;
#pragma unroll
        for (int j = 0; j < 4; j++) {
            int c0 = bn + wn + j * 8 + 2 * lr;
            float2 v0 = make_float2(acc[i][j][0], acc[i][j][1]);
            float2 v1 = make_float2(acc[i][j][2], acc[i][j][3]);
            *(float2*)&C[(size_t)r0 * ldc + c0]       = v0;
            *(float2*)&C[(size_t)(r0 + 8) * ldc + c0] = v1;
        }
    }
}

// ---------------- top-2 helper ----------------------------------------------
__device__ __forceinline__ void top2_of5(const float g[5], int& i1, int& i2) {
    i1 = 0;
#pragma unroll
    for (int e = 1; e < 5; e++) if (g[e] > g[i1]) i1 = e;
    i2 = (i1 == 0) ? 1 : 0;
#pragma unroll
    for (int e = 0; e < 5; e++) if (e != i1 && g[e] > g[i2]) i2 = e;
}

// ---------------- V combine: v[bt, h*64+d] = sum_top2 sigmoid(gl)*xv --------
__global__ void v_combine_kernel(const float* __restrict__ proj, float* __restrict__ v)
{
    int idx = blockIdx.x * 256 + threadIdx.x;
    if (idx >= BT * HH * DHH) return;
    int d  = idx & (DHH - 1);
    int h  = (idx >> 6) & (HH - 1);
    int bt = idx >> 9;
    const float* g = proj + (size_t)bt * NBIG + C_GLV + h * EE;
    float ga[5] = { g[0], g[1], g[2], g[3], g[4] };
    int i1, i2;
    top2_of5(ga, i1, i2);
    float w1 = 1.f / (1.f + __expf(-ga[i1]));
    float w2 = 1.f / (1.f + __expf(-ga[i2]));
    const float* xv = proj + (size_t)bt * NBIG + C_XV;
    v[(size_t)bt * HD + h * DHH + d] = w1 * xv[i1 * DHH + d] + w2 * xv[i2 * DHH + d];
}

// ---------------- flash attention (fp32, 1 thread = 1 q row) ----------------
__global__ __launch_bounds__(128) void flash_attn_kernel(
    const float* __restrict__ proj, const float* __restrict__ v, float* __restrict__ attn)
{
    const int h = blockIdx.y & (HH - 1);
    const int b = blockIdx.y >> 3;
    const int row = blockIdx.x * 128 + threadIdx.x;
    __shared__ float Ks[32][64];
    __shared__ float Vs[32][64];

    const size_t btq = (size_t)(b * TT + row);
    float qr[DHH];
#pragma unroll
    for (int d = 0; d < DHH; d++)
        qr[d] = proj[btq * NBIG + C_Q + h * DHH + d] * 0.125f;

    float o[DHH];
#pragma unroll
    for (int d = 0; d < DHH; d++) o[d] = 0.f;
    float mrun = -1e30f, lrun = 0.f;

    for (int j0 = 0; j0 < TT; j0 += 32) {
        __syncthreads();
        for (int i = threadIdx.x; i < 32 * 64; i += 128) {
            int jj = i >> 6, d = i & 63;
            size_t btk = (size_t)(b * TT + j0 + jj);
            Ks[jj][d] = proj[btk * NBIG + C_K + h * DHH + d];
            Vs[jj][d] = v[btk * HD + h * DHH + d];
        }
        __syncthreads();

        float s[32];
        float mnew = mrun;
#pragma unroll 4
        for (int jj = 0; jj < 32; jj++) {
            const float4* kr = (const float4*)Ks[jj];
            float a0 = 0.f, a1 = 0.f, a2 = 0.f, a3 = 0.f;
#pragma unroll
            for (int d4 = 0; d4 < 16; d4++) {
                float4 kk = kr[d4];
                a0 += qr[4 * d4 + 0] * kk.x;
                a1 += qr[4 * d4 + 1] * kk.y;
                a2 += qr[4 * d4 + 2] * kk.z;
                a3 += qr[4 * d4 + 3] * kk.w;
            }
            s[jj] = (a0 + a1) + (a2 + a3);
            mnew = fmaxf(mnew, s[jj]);
        }
        float corr = __expf(mrun - mnew);
        lrun *= corr;
#pragma unroll
        for (int d = 0; d < DHH; d++) o[d] *= corr;
#pragma unroll 2
        for (int jj = 0; jj < 32; jj++) {
            float p = __expf(s[jj] - mnew);
            lrun += p;
            const float4* vr = (const float4*)Vs[jj];
#pragma unroll
            for (int d4 = 0; d4 < 16; d4++) {
                float4 vv = vr[d4];
                o[4 * d4 + 0] += p * vv.x; o[4 * d4 + 1] += p * vv.y;
                o[4 * d4 + 2] += p * vv.z; o[4 * d4 + 3] += p * vv.w;
            }
        }
        mrun = mnew;
    }
    float inv = 1.f / lrun;
#pragma unroll
    for (int d = 0; d < DHH; d++)
        attn[btq * HD + h * DHH + d] = o[d] * inv;
}

// ---------------- out-gate aggregation: agg[bt,e,d] = sum_h mask*attn -------
__global__ void out_gate_kernel(const float* __restrict__ proj,
                                const float* __restrict__ attn,
                                float* __restrict__ agg)
{
    int idx = blockIdx.x * 256 + threadIdx.x;
    if (idx >= BT * EE * DHH) return;
    int d  = idx % DHH;
    int e  = (idx / DHH) % EE;
    int bt = idx / (EE * DHH);
    float sum = 0.f;
#pragma unroll
    for (int h = 0; h < HH; h++) {
        const float* g = proj + (size_t)bt * NBIG + C_GLO + h * EE;
        float ga[5] = { g[0], g[1], g[2], g[3], g[4] };
        int i1, i2;
        top2_of5(ga, i1, i2);
        if (e == i1 || e == i2) sum += attn[(size_t)bt * HD + h * DHH + d];
    }
    agg[idx] = sum;
}

// ---------------- launcher ---------------------------------------------------
extern "C" void kernel_launch(void* const* d_in, const int* in_sizes, int n_in,
                              void* d_out, int out_size)
{
    const float* x  = (const float*)d_in[0];
    const float* Wq = (const float*)d_in[1];
    const float* Wk = (const float*)d_in[2];
    const float* Ws = (const float*)d_in[3];
    const float* Wd = (const float*)d_in[4];
    const float* Wv = (const float*)d_in[5];
    const float* Wo = (const float*)d_in[6];
    float* out = (float*)d_out;

    float *Bbig, *proj, *v, *attn, *agg;
    cudaGetSymbolAddress((void**)&Bbig, g_Bbig);
    cudaGetSymbolAddress((void**)&proj, g_proj);
    cudaGetSymbolAddress((void**)&v,    g_v);
    cudaGetSymbolAddress((void**)&attn, g_at);
    cudaGetSymbolAddress((void**)&agg,  g_agg);

    cudaFuncSetAttribute(tf32_gemm_kernel,
                         cudaFuncAttributeMaxDynamicSharedMemorySize, GEMM_SMEM_BYTES);

    // Build fused projection weight matrix (fp32)
    {
        int nb = DD * NBIG;
        pack_bbig_kernel<<<(nb + 255) / 256, 256>>>(Wq, Wk, Ws, Wd, Wv, Bbig);
    }

    // Fused projection GEMM: proj[8192,1536] = x[8192,1024] @ Bbig[1024,1536]
    tf32_gemm_kernel<<<dim3(NBIG / 128, BT / 128), 256, GEMM_SMEM_BYTES>>>(
        x, Bbig, proj, BT, NBIG, DD, DD, NBIG, NBIG);

    // V combine (top-2 sigmoid gating)
    {
        int n = BT * HH * DHH;
        v_combine_kernel<<<(n + 255) / 256, 256>>>(proj, v);
    }

    // Flash attention
    flash_attn_kernel<<<dim3(TT / 128, BB * HH), 128>>>(proj, v, attn);

    // Output-gate aggregation over heads
    {
        int n = BT * EE * DHH;
        out_gate_kernel<<<(n + 255) / 256, 256>>>(proj, attn, agg);
    }

    // Output expert GEMM: out[8192,1024] = agg[8192,320] @ Wo[320,1024]
    // (Wo viewed as (E*DH, D) row-major is exactly the B layout we need)
    tf32_gemm_kernel<<<dim3(DD / 128, BT / 128), 256, GEMM_SMEM_BYTES>>>(
        agg, Wo, out, BT, DD, EE * DHH, EE * DHH, DD, DD);
}

// round 5
// speedup vs baseline: 8.9246x; 2.6368x over previous
#include <cuda_runtime.h>
#include <cstdint>

#define BB   4
#define TT   2048
#define DD   1024
#define HH   8
#define DHH  64
#define EE   5
#define BT   (BB*TT)     // 8192
#define HD   (HH*DHH)    // 512
#define NPROJ 1408       // [q 512 | k 512 | xv 320 | pad 64]
#define NGATE 128        // [glv 40 | glo 40 | pad 48]
#define C_Q   0
#define C_K   512
#define C_XV  1024
#define G_GLV 0
#define G_GLO 40

// ---------------- scratch (device globals; no allocations allowed) ----------
__device__ float g_Bbig[DD*NPROJ];     // packed [Wq|Wk|Wv|0] fp32
__device__ float g_Bg  [DD*NGATE];     // packed [Ws|Wd|0] fp32
__device__ float g_proj[BT*NPROJ];     // q/k/xv (tf32-rounded fp32)
__device__ float g_glg [BT*NGATE];     // gate logits (3xtf32 accurate)
__device__ float g_v   [BT*HD];        // combined V (tf32-rounded)
__device__ float g_at  [BT*HD];
__device__ float g_agg [BT*EE*DHH];

// ---------------- helpers ----------------------------------------------------
__device__ __forceinline__ uint32_t f2tf32(float x) {
    uint32_t r;
    asm("cvt.rna.tf32.f32 %0, %1;" : "=r"(r) : "f"(x));
    return r;
}
__device__ __forceinline__ void tf32_split(float x, uint32_t& hi, uint32_t& lo) {
    hi = f2tf32(x);
    lo = f2tf32(x - __uint_as_float(hi));
}
__device__ __forceinline__ float ex2(float x) {
    float r; asm("ex2.approx.ftz.f32 %0, %1;" : "=f"(r) : "f"(x)); return r;
}
__device__ __forceinline__ void cp_async16(uint32_t s, const void* g) {
    asm volatile("cp.async.cg.shared.global [%0], [%1], 16;" :: "r"(s), "l"(g));
}
__device__ __forceinline__ void cp_commit() { asm volatile("cp.async.commit_group;"); }
__device__ __forceinline__ void cp_wait0()  { asm volatile("cp.async.wait_group 0;"); }
__device__ __forceinline__ void cp_wait1()  { asm volatile("cp.async.wait_group 1;"); }
__device__ __forceinline__ void mma_tf32(float* c, const uint32_t* a, const uint32_t* b) {
    asm volatile(
        "mma.sync.aligned.m16n8k8.row.col.f32.tf32.tf32.f32 "
        "{%0,%1,%2,%3}, {%4,%5,%6,%7}, {%8,%9}, {%0,%1,%2,%3};"
        : "+f"(c[0]), "+f"(c[1]), "+f"(c[2]), "+f"(c[3])
        : "r"(a[0]), "r"(a[1]), "r"(a[2]), "r"(a[3]), "r"(b[0]), "r"(b[1]));
}

// ---------------- pack kernels ----------------------------------------------
__global__ void pack_bbig_kernel(const float* __restrict__ Wq, const float* __restrict__ Wk,
                                 const float* __restrict__ Wv, float* __restrict__ Bb) {
    int idx = blockIdx.x * 256 + threadIdx.x;
    if (idx >= DD * NPROJ) return;
    int d = idx / NPROJ, c = idx % NPROJ;
    float v = 0.f;
    if      (c < 512)  v = Wq[d * 512 + c];
    else if (c < 1024) v = Wk[d * 512 + c - 512];
    else if (c < 1344) {
        int cc = c - 1024;
        int e = cc >> 6, kk = cc & 63;
        v = Wv[((size_t)e * DD + d) * 64 + kk];
    }
    Bb[idx] = v;
}
__global__ void pack_bg_kernel(const float* __restrict__ Ws, const float* __restrict__ Wd,
                               float* __restrict__ Bg) {
    int idx = blockIdx.x * 256 + threadIdx.x;
    if (idx >= DD * NGATE) return;
    int d = idx / NGATE, c = idx % NGATE;
    float v = 0.f;
    if      (c < 40) v = Ws[d * 40 + c];
    else if (c < 80) v = Wd[d * 40 + c - 40];
    Bg[idx] = v;
}

// ---------------- tf32 tensor-core GEMM (templated 1x / 3x, optional round) -
#define SA_STRIDE 36
#define SB_STRIDE 136
#define SA_FLOATS (128*SA_STRIDE)
#define SB_FLOATS (32*SB_STRIDE)
#define GEMM_SMEM_BYTES ((2*SA_FLOATS + 2*SB_FLOATS)*4)  // 71680

template<int SPLIT, bool ROUND>
__global__ __launch_bounds__(256) void tf32_gemm_kernel(
    const float* __restrict__ A, const float* __restrict__ B, float* __restrict__ C,
    int M, int N, int K, int lda, int ldb, int ldc)
{
    extern __shared__ float smem[];
    float* sA = smem;
    float* sB = smem + 2 * SA_FLOATS;

    const int tid  = threadIdx.x;
    const int warp = tid >> 5, lane = tid & 31;
    const int lq = lane >> 2, lr = lane & 3;
    const int wm = (warp & 1) * 64;
    const int wn = (warp >> 1) * 32;
    const int bm = blockIdx.y * 128;
    const int bn = blockIdx.x * 128;

    float acc[4][4][4];
#pragma unroll
    for (int i = 0; i < 4; i++)
#pragma unroll
        for (int j = 0; j < 4; j++)
#pragma unroll
            for (int v = 0; v < 4; v++) acc[i][j][v] = 0.f;

    const uint32_t sA_base = (uint32_t)__cvta_generic_to_shared(sA);
    const uint32_t sB_base = (uint32_t)__cvta_generic_to_shared(sB);

#define COPY_STAGE(buf, k0)                                                     \
    {                                                                           \
        _Pragma("unroll")                                                       \
        for (int it = 0; it < 4; it++) {                                        \
            int f = tid + it * 256;                                             \
            int ar = f >> 3, ac4 = f & 7;                                       \
            cp_async16(sA_base + ((buf) * SA_FLOATS + ar * SA_STRIDE + ac4 * 4) * 4, \
                       A + (size_t)(bm + ar) * lda + (k0) + ac4 * 4);           \
            int br = f >> 5, bc4 = f & 31;                                      \
            cp_async16(sB_base + ((buf) * SB_FLOATS + br * SB_STRIDE + bc4 * 4) * 4, \
                       B + (size_t)((k0) + br) * ldb + bn + bc4 * 4);           \
        }                                                                       \
    }

    const int nk = K >> 5;
    COPY_STAGE(0, 0);
    cp_commit();

    for (int kt = 0; kt < nk; kt++) {
        if (kt + 1 < nk) {
            COPY_STAGE((kt + 1) & 1, (kt + 1) << 5);
            cp_commit();
            cp_wait1();
        } else {
            cp_wait0();
        }
        __syncthreads();

        const float* cA = sA + (kt & 1) * SA_FLOATS;
        const float* cB = sB + (kt & 1) * SB_FLOATS;
#pragma unroll
        for (int s = 0; s < 4; s++) {
            uint32_t ah[4][4], al[4][4], bh[4][2], bl[4][2];
#pragma unroll
            for (int i = 0; i < 4; i++) {
                int base = (wm + i * 16 + lq) * SA_STRIDE + s * 8 + lr;
                if (SPLIT == 3) {
                    tf32_split(cA[base],                  ah[i][0], al[i][0]);
                    tf32_split(cA[base + 8 * SA_STRIDE],  ah[i][1], al[i][1]);
                    tf32_split(cA[base + 4],              ah[i][2], al[i][2]);
                    tf32_split(cA[base + 8*SA_STRIDE+4],  ah[i][3], al[i][3]);
                } else {
                    ah[i][0] = f2tf32(cA[base]);
                    ah[i][1] = f2tf32(cA[base + 8 * SA_STRIDE]);
                    ah[i][2] = f2tf32(cA[base + 4]);
                    ah[i][3] = f2tf32(cA[base + 8*SA_STRIDE+4]);
                }
            }
#pragma unroll
            for (int j = 0; j < 4; j++) {
                int base = (s * 8 + lr) * SB_STRIDE + wn + j * 8 + lq;
                if (SPLIT == 3) {
                    tf32_split(cB[base],                  bh[j][0], bl[j][0]);
                    tf32_split(cB[base + 4 * SB_STRIDE],  bh[j][1], bl[j][1]);
                } else {
                    bh[j][0] = f2tf32(cB[base]);
                    bh[j][1] = f2tf32(cB[base + 4 * SB_STRIDE]);
                }
            }
#pragma unroll
            for (int i = 0; i < 4; i++)
#pragma unroll
                for (int j = 0; j < 4; j++) {
                    if (SPLIT == 3) {
                        mma_tf32(acc[i][j], ah[i], bl[j]);
                        mma_tf32(acc[i][j], al[i], bh[j]);
                    }
                    mma_tf32(acc[i][j], ah[i], bh[j]);
                }
        }
        __syncthreads();
    }
#undef COPY_STAGE

#pragma unroll
    for (int i = 0; i < 4; i++) {
        int r0 = bm + wm + i * 16 + lq;
#pragma unroll
        for (int j = 0; j < 4; j++) {
            int c0 = bn + wn + j * 8 + 2 * lr;
            float v0, v1, v2, v3;
            if (ROUND) {
                v0 = __uint_as_float(f2tf32(acc[i][j][0]));
                v1 = __uint_as_float(f2tf32(acc[i][j][1]));
                v2 = __uint_as_float(f2tf32(acc[i][j][2]));
                v3 = __uint_as_float(f2tf32(acc[i][j][3]));
            } else {
                v0 = acc[i][j][0]; v1 = acc[i][j][1];
                v2 = acc[i][j][2]; v3 = acc[i][j][3];
            }
            *(float2*)&C[(size_t)r0 * ldc + c0]       = make_float2(v0, v1);
            *(float2*)&C[(size_t)(r0 + 8) * ldc + c0] = make_float2(v2, v3);
        }
    }
}

// ---------------- top-2 helper ----------------------------------------------
__device__ __forceinline__ void top2_of5(const float g[5], int& i1, int& i2) {
    i1 = 0;
#pragma unroll
    for (int e = 1; e < 5; e++) if (g[e] > g[i1]) i1 = e;
    i2 = (i1 == 0) ? 1 : 0;
#pragma unroll
    for (int e = 0; e < 5; e++) if (e != i1 && g[e] > g[i2]) i2 = e;
}

// ---------------- V combine (tf32-rounded output for tensor-core attn) ------
__global__ void v_combine_kernel(const float* __restrict__ glg,
                                 const float* __restrict__ proj, float* __restrict__ v)
{
    int idx = blockIdx.x * 256 + threadIdx.x;
    if (idx >= BT * HH * DHH) return;
    int d  = idx & (DHH - 1);
    int h  = (idx >> 6) & (HH - 1);
    int bt = idx >> 9;
    const float* g = glg + (size_t)bt * NGATE + G_GLV + h * EE;
    float ga[5] = { g[0], g[1], g[2], g[3], g[4] };
    int i1, i2;
    top2_of5(ga, i1, i2);
    float w1 = 1.f / (1.f + __expf(-ga[i1]));
    float w2 = 1.f / (1.f + __expf(-ga[i2]));
    const float* xv = proj + (size_t)bt * NPROJ + C_XV;
    float r = w1 * xv[i1 * DHH + d] + w2 * xv[i2 * DHH + d];
    v[(size_t)bt * HD + h * DHH + d] = __uint_as_float(f2tf32(r));
}

// ---------------- tensor-core flash attention --------------------------------
// grid (T/128, B*H), 256 thr = 8 warps, warp = 16 q rows; KV tiles of 64.
#define KSTRIDE 68
#define VSTRIDE 72
#define FL_SMEM ((2*64*KSTRIDE + 2*64*VSTRIDE)*4)   // 71680

__global__ __launch_bounds__(256) void flash_attn_tc_kernel(
    const float* __restrict__ proj, const float* __restrict__ v, float* __restrict__ attn)
{
    extern __shared__ float fsm[];
    float* sK = fsm;                  // [2][64][KSTRIDE]
    float* sV = fsm + 2*64*KSTRIDE;   // [2][64][VSTRIDE]
    const int tid  = threadIdx.x;
    const int warp = tid >> 5, lane = tid & 31;
    const int lq = lane >> 2, lr = lane & 3;
    const int h = blockIdx.y & 7, b = blockIdx.y >> 3;
    const int qbase = blockIdx.x * 128 + warp * 16;

    const uint32_t sKu = (uint32_t)__cvta_generic_to_shared(sK);
    const uint32_t sVu = (uint32_t)__cvta_generic_to_shared(sV);

    // Q fragments, pre-scaled by 1/8 * log2(e) so softmax uses exp2
    const float QS = 0.1803368801f;
    uint32_t qa[8][4];
    {
        const float* pa = proj + (size_t)(b*TT + qbase + lq) * NPROJ + C_Q + h*64;
        const float* pb = pa + (size_t)8 * NPROJ;
#pragma unroll
        for (int kc = 0; kc < 8; kc++) {
            qa[kc][0] = f2tf32(QS * pa[kc*8 + lr]);
            qa[kc][1] = f2tf32(QS * pb[kc*8 + lr]);
            qa[kc][2] = f2tf32(QS * pa[kc*8 + lr + 4]);
            qa[kc][3] = f2tf32(QS * pb[kc*8 + lr + 4]);
        }
    }

    float o[8][4];
#pragma unroll
    for (int nt = 0; nt < 8; nt++) { o[nt][0]=o[nt][1]=o[nt][2]=o[nt][3]=0.f; }
    float m_lo = -1e30f, m_hi = -1e30f, l_lo = 0.f, l_hi = 0.f;

    const float* Kg = proj + (size_t)b*TT*NPROJ + C_K + h*64;   // row stride NPROJ
    const float* Vg = v    + (size_t)b*TT*HD   + h*64;          // row stride HD

    // FIX (R5): a 64x64 fp32 tile = 1024 16B segments; 256 threads x 4 copies.
#define LOAD_TILE(buf, j0)                                                      \
    {                                                                           \
        _Pragma("unroll")                                                       \
        for (int it = 0; it < 4; it++) {                                        \
            int f = tid + it * 256;                                             \
            int krow = f >> 4, kseg = f & 15;                                   \
            cp_async16(sKu + ((buf)*64*KSTRIDE + krow*KSTRIDE + kseg*4)*4,      \
                       Kg + (size_t)((j0)+krow)*NPROJ + kseg*4);                \
            cp_async16(sVu + ((buf)*64*VSTRIDE + krow*VSTRIDE + kseg*4)*4,      \
                       Vg + (size_t)((j0)+krow)*HD + kseg*4);                   \
        }                                                                       \
    }

    LOAD_TILE(0, 0);
    cp_commit();

    for (int kt = 0; kt < TT/64; kt++) {
        if (kt + 1 < TT/64) { LOAD_TILE((kt+1)&1, (kt+1)*64); cp_commit(); cp_wait1(); }
        else cp_wait0();
        __syncthreads();

        const float* cK = sK + (kt & 1) * 64 * KSTRIDE;
        const float* cV = sV + (kt & 1) * 64 * VSTRIDE;

        // S = Q @ K^T  (scores, c-layout)
        float sc[8][4];
#pragma unroll
        for (int nt = 0; nt < 8; nt++) { sc[nt][0]=sc[nt][1]=sc[nt][2]=sc[nt][3]=0.f; }
#pragma unroll
        for (int kc = 0; kc < 8; kc++) {
#pragma unroll
            for (int nt = 0; nt < 8; nt++) {
                uint32_t bf[2];
                bf[0] = __float_as_uint(cK[(nt*8+lq)*KSTRIDE + kc*8 + lr]);
                bf[1] = __float_as_uint(cK[(nt*8+lq)*KSTRIDE + kc*8 + lr + 4]);
                mma_tf32(sc[nt], qa[kc], bf);
            }
        }

        // online softmax (rows lq and lq+8)
        float mxl = m_lo, mxh = m_hi;
#pragma unroll
        for (int nt = 0; nt < 8; nt++) {
            mxl = fmaxf(mxl, fmaxf(sc[nt][0], sc[nt][1]));
            mxh = fmaxf(mxh, fmaxf(sc[nt][2], sc[nt][3]));
        }
        mxl = fmaxf(mxl, __shfl_xor_sync(0xffffffffu, mxl, 1));
        mxl = fmaxf(mxl, __shfl_xor_sync(0xffffffffu, mxl, 2));
        mxh = fmaxf(mxh, __shfl_xor_sync(0xffffffffu, mxh, 1));
        mxh = fmaxf(mxh, __shfl_xor_sync(0xffffffffu, mxh, 2));
        float cl = ex2(m_lo - mxl), ch = ex2(m_hi - mxh);
        float sl = 0.f, sh = 0.f;
#pragma unroll
        for (int nt = 0; nt < 8; nt++) {
            sc[nt][0] = ex2(sc[nt][0] - mxl); sl += sc[nt][0];
            sc[nt][1] = ex2(sc[nt][1] - mxl); sl += sc[nt][1];
            sc[nt][2] = ex2(sc[nt][2] - mxh); sh += sc[nt][2];
            sc[nt][3] = ex2(sc[nt][3] - mxh); sh += sc[nt][3];
        }
        sl += __shfl_xor_sync(0xffffffffu, sl, 1);
        sl += __shfl_xor_sync(0xffffffffu, sl, 2);
        sh += __shfl_xor_sync(0xffffffffu, sh, 1);
        sh += __shfl_xor_sync(0xffffffffu, sh, 2);
        l_lo = l_lo * cl + sl;
        l_hi = l_hi * ch + sh;
        m_lo = mxl; m_hi = mxh;
#pragma unroll
        for (int nt = 0; nt < 8; nt++) {
            o[nt][0] *= cl; o[nt][1] *= cl;
            o[nt][2] *= ch; o[nt][3] *= ch;
        }

        // O += P @ V  (convert P c-layout -> a-layout via intra-quad shuffles)
        const int srcA = (lane & ~3) | (lr >> 1);
        const bool odd = (lane & 1);
#pragma unroll
        for (int kc = 0; kc < 8; kc++) {
            float q0 = __shfl_sync(0xffffffffu, sc[kc][0], srcA);
            float q1 = __shfl_sync(0xffffffffu, sc[kc][1], srcA);
            float q2 = __shfl_sync(0xffffffffu, sc[kc][2], srcA);
            float q3 = __shfl_sync(0xffffffffu, sc[kc][3], srcA);
            float r0 = __shfl_sync(0xffffffffu, sc[kc][0], srcA + 2);
            float r1 = __shfl_sync(0xffffffffu, sc[kc][1], srcA + 2);
            float r2 = __shfl_sync(0xffffffffu, sc[kc][2], srcA + 2);
            float r3 = __shfl_sync(0xffffffffu, sc[kc][3], srcA + 2);
            uint32_t pa[4];
            pa[0] = f2tf32(odd ? q1 : q0);
            pa[1] = f2tf32(odd ? q3 : q2);
            pa[2] = f2tf32(odd ? r1 : r0);
            pa[3] = f2tf32(odd ? r3 : r2);
#pragma unroll
            for (int nt = 0; nt < 8; nt++) {
                uint32_t bf[2];
                bf[0] = __float_as_uint(cV[(kc*8+lr)*VSTRIDE + nt*8 + lq]);
                bf[1] = __float_as_uint(cV[(kc*8+lr+4)*VSTRIDE + nt*8 + lq]);
                mma_tf32(o[nt], pa, bf);
            }
        }
        __syncthreads();
    }
#undef LOAD_TILE

    float il = 1.f / l_lo, ih = 1.f / l_hi;
    float* oa = attn + (size_t)(b*TT + qbase + lq) * HD + h*64;
    float* ob = attn + (size_t)(b*TT + qbase + lq + 8) * HD + h*64;
#pragma unroll
    for (int nt = 0; nt < 8; nt++) {
        *(float2*)&oa[nt*8 + 2*lr] = make_float2(o[nt][0]*il, o[nt][1]*il);
        *(float2*)&ob[nt*8 + 2*lr] = make_float2(o[nt][2]*ih, o[nt][3]*ih);
    }
}

// ---------------- out-gate aggregation ---------------------------------------
__global__ void out_gate_kernel(const float* __restrict__ glg,
                                const float* __restrict__ attn,
                                float* __restrict__ agg)
{
    int idx = blockIdx.x * 256 + threadIdx.x;
    if (idx >= BT * EE * DHH) return;
    int d  = idx % DHH;
    int e  = (idx / DHH) % EE;
    int bt = idx / (EE * DHH);
    float sum = 0.f;
#pragma unroll
    for (int h = 0; h < HH; h++) {
        const float* g = glg + (size_t)bt * NGATE + G_GLO + h * EE;
        float ga[5] = { g[0], g[1], g[2], g[3], g[4] };
        int i1, i2;
        top2_of5(ga, i1, i2);
        if (e == i1 || e == i2) sum += attn[(size_t)bt * HD + h * DHH + d];
    }
    agg[idx] = sum;
}

// ---------------- launcher ---------------------------------------------------
extern "C" void kernel_launch(void* const* d_in, const int* in_sizes, int n_in,
                              void* d_out, int out_size)
{
    const float* x  = (const float*)d_in[0];
    const float* Wq = (const float*)d_in[1];
    const float* Wk = (const float*)d_in[2];
    const float* Ws = (const float*)d_in[3];
    const float* Wd = (const float*)d_in[4];
    const float* Wv = (const float*)d_in[5];
    const float* Wo = (const float*)d_in[6];
    float* out = (float*)d_out;

    float *Bbig, *Bg, *proj, *glg, *v, *attn, *agg;
    cudaGetSymbolAddress((void**)&Bbig, g_Bbig);
    cudaGetSymbolAddress((void**)&Bg,   g_Bg);
    cudaGetSymbolAddress((void**)&proj, g_proj);
    cudaGetSymbolAddress((void**)&glg,  g_glg);
    cudaGetSymbolAddress((void**)&v,    g_v);
    cudaGetSymbolAddress((void**)&attn, g_at);
    cudaGetSymbolAddress((void**)&agg,  g_agg);

    cudaFuncSetAttribute(tf32_gemm_kernel<1, true>,
                         cudaFuncAttributeMaxDynamicSharedMemorySize, GEMM_SMEM_BYTES);
    cudaFuncSetAttribute(tf32_gemm_kernel<3, false>,
                         cudaFuncAttributeMaxDynamicSharedMemorySize, GEMM_SMEM_BYTES);
    cudaFuncSetAttribute(flash_attn_tc_kernel,
                         cudaFuncAttributeMaxDynamicSharedMemorySize, FL_SMEM);

    // Pack weights
    {
        int nb = DD * NPROJ;
        pack_bbig_kernel<<<(nb + 255) / 256, 256>>>(Wq, Wk, Wv, Bbig);
        int ng = DD * NGATE;
        pack_bg_kernel<<<(ng + 255) / 256, 256>>>(Ws, Wd, Bg);
    }

    // q/k/xv projection (1xtf32, outputs rounded to tf32 for the attn mma)
    tf32_gemm_kernel<1, true><<<dim3(NPROJ / 128, BT / 128), 256, GEMM_SMEM_BYTES>>>(
        x, Bbig, proj, BT, NPROJ, DD, DD, NPROJ, NPROJ);
    // gate projection (3xtf32 — top-k selection must be exact)
    tf32_gemm_kernel<3, false><<<dim3(NGATE / 128, BT / 128), 256, GEMM_SMEM_BYTES>>>(
        x, Bg, glg, BT, NGATE, DD, DD, NGATE, NGATE);

    // V combine (top-2 sigmoid gating; tf32-rounded output)
    {
        int n = BT * HH * DHH;
        v_combine_kernel<<<(n + 255) / 256, 256>>>(glg, proj, v);
    }

    // Tensor-core flash attention
    flash_attn_tc_kernel<<<dim3(TT / 128, BB * HH), 256, FL_SMEM>>>(proj, v, attn);

    // Output-gate aggregation over heads
    {
        int n = BT * EE * DHH;
        out_gate_kernel<<<(n + 255) / 256, 256>>>(glg, attn, agg);
    }

    // Output expert GEMM: out = agg[8192,320] @ Wo[320,1024]  (3xtf32)
    tf32_gemm_kernel<3, false><<<dim3(DD / 128, BT / 128), 256, GEMM_SMEM_BYTES>>>(
        agg, Wo, out, BT, DD, EE * DHH, EE * DHH, DD, DD);
}